// round 17
// baseline (speedup 1.0000x reference)
#include <cuda_runtime.h>
#include <cuda_bf16.h>

// SmoothLDDTLoss — b=2, n=4096. Single fused kernel.
// R16 inner loop (dot-product distances, select mask, byte-offset baked
// 256-bin LUT, IR=2, unroll 2, 48 regs) with TJ=64: 1088 CTAs, one wave at
// 10 CTAs/SM, half the per-CTA fixed overhead of R16's 2176-CTA grid.

#define NTOK 4096
#define TJ 64
#define TI 256
#define BLK 128
#define NTILES_B 544              // sum_{I=0}^{15} (64 - 4I)
#define TOTAL_CTAS (2 * NTILES_B)

#define TBL_N 256
#define TBL_H 0.0625f             // 16 / 256
#define DD_CLAMP 15.9375f         // 255 * H
#define MASK_BIG 2097152.0f       // 2^21 >> max cutoff^2 (900)

__device__ double g_acc[4];       // [num0, den0, num1, den1]
__device__ int g_done;

__device__ __forceinline__ float fsqrt_approx(float x) {
    float r; asm("sqrt.approx.f32 %0, %1;" : "=f"(r) : "f"(x)); return r;
}

// sum of 4 sigmoids sigma(t - x), t in {0.5,1,2,4}; rational: 1 exp + 1 div
__device__ __forceinline__ float sig4c(float x) {
    const float C0 = 0.60653066f, C1 = 0.36787944f, C2 = 0.13533528f, C3 = 0.018315639f;
    float e = __expf(x);
    float b0 = fmaf(e, C0, 1.0f), b1 = fmaf(e, C1, 1.0f);
    float b2 = fmaf(e, C2, 1.0f), b3 = fmaf(e, C3, 1.0f);
    float p01 = b0 * b1, p23 = b2 * b3;
    float numr = fmaf(b0 + b1, p23, (b2 + b3) * p01);
    return __fdividef(numr, p01 * p23);
}

struct RowS {
    float ax, ay, az, sp;   // -2*pred_i, |pred_i|^2
    float bx, by, bz, st;   // -2*true_i, |true_i|^2
    float nuc;              // 1 if nucleotide else 0
};

// one pair, dot-product form. A=(px,py,pz,|p|^2), B=(tx,ty,tz,|t|^2+maskbig), cj=675*wp_j
__device__ __forceinline__ void pair_dot(
    const RowS& r, float4 A, float4 B, float cj,
    const float2* __restrict__ tbl, float& num, float& den, bool active)
{
    float d2p = fmaf(r.ax, A.x, fmaf(r.ay, A.y, fmaf(r.az, A.z, r.sp))) + A.w;
    float d2t = fmaf(r.bx, B.x, fmaf(r.by, B.y, fmaf(r.bz, B.z, r.st))) + B.w;

    float cut2 = fmaf(r.nuc, cj, 225.0f);               // 225 or 900
    float mm = (d2t < cut2 && active) ? 1.0f : 0.0f;

    // fminf is the NaN guard: sqrt.approx(rounding-negative d2) -> NaN,
    // fminf(NaN, C) -> C. Do NOT remove.
    float dd = fminf(fabsf(fsqrt_approx(d2t) - fsqrt_approx(d2p)), DD_CLAMP);
    // direct float2 byte offset: (int(dd*16) & 255) * 8, via magic FFMA
    int boff = __float_as_int(fmaf(dd, 128.0f, 8388608.0f)) & 0x7F8;
    float2 e = *(const float2*)((const char*)tbl + boff);
    float v = fmaf(dd, e.y, e.x);                       // = 4 * eps

    num = fmaf(v, mm, num);
    den += mm;
}

__global__ void __launch_bounds__(BLK)
lddt_fused(const float* __restrict__ pred,
           const float* __restrict__ truec,
           const int* __restrict__ is_dna,
           const int* __restrict__ is_rna,
           const int* __restrict__ cmask,
           float* __restrict__ out)
{
    // decode (batch, I, Jh): i-row I (16 rows of 256) has 64 - 4I 64-wide
    // j-tiles, Jh = 4I + lin
    int lin = blockIdx.x;
    const int b = (lin >= NTILES_B) ? 1 : 0;
    lin -= b * NTILES_B;
    int I = 0;
    {
        int cnt = 64;
        while (lin >= cnt) { lin -= cnt; I++; cnt -= 4; }
    }
    const int Jh = 4 * I + lin;
    const bool hot = (lin >= 4);       // tile fully above both row groups

    const int tid = threadIdx.x;

    __shared__ float2 tbl[TBL_N];      // (v_k - k*s_k, s_k/H)
    __shared__ float vraw[TBL_N + 1];  // raw sig4 node values
    __shared__ float4 sA[TJ];          // pred xyz, |p|^2
    __shared__ float4 sB[TJ];          // true xyz, |t|^2 + (wt?0:BIG)
    __shared__ float  sC[TJ];          // 675 * wp_j

    for (int k = tid; k < TBL_N; k += BLK)
        vraw[k] = sig4c((float)k * TBL_H);
    if (tid == 0) vraw[TBL_N] = sig4c(16.0f);

    const int base = b * NTOK;

    if (tid < TJ) {
        const int jg = base + Jh * TJ + tid;
        float px = pred[3 * jg + 0], py = pred[3 * jg + 1], pz = pred[3 * jg + 2];
        float tx = truec[3 * jg + 0], ty = truec[3 * jg + 1], tz = truec[3 * jg + 2];
        float np = fmaf(px, px, fmaf(py, py, pz * pz));
        float nt = fmaf(tx, tx, fmaf(ty, ty, tz * tz));
        bool wt = (cmask[jg] != 0);
        sA[tid] = make_float4(px, py, pz, np);
        sB[tid] = make_float4(tx, ty, tz, wt ? nt : nt + MASK_BIG);
        sC[tid] = (is_dna[jg] != 0 || is_rna[jg] != 0) ? 675.0f : 0.0f;
    }
    __syncthreads();

    // bake (base, slope/H) per bin
    for (int k = tid; k < TBL_N; k += BLK) {
        float v0 = vraw[k];
        float s = vraw[k + 1] - v0;
        tbl[k] = make_float2(fmaf(-(float)k, s, v0), s * 16.0f);
    }

    // own rows: r0 = 256*I + tid, r1 = r0 + 128
    const int ig0 = base + I * TI + tid;
    const int ig1 = ig0 + BLK;
    RowS r0, r1;
    {
        float px = pred[3 * ig0 + 0], py = pred[3 * ig0 + 1], pz = pred[3 * ig0 + 2];
        float tx = truec[3 * ig0 + 0], ty = truec[3 * ig0 + 1], tz = truec[3 * ig0 + 2];
        r0.ax = -2.0f * px; r0.ay = -2.0f * py; r0.az = -2.0f * pz;
        r0.sp = fmaf(px, px, fmaf(py, py, pz * pz));
        r0.bx = -2.0f * tx; r0.by = -2.0f * ty; r0.bz = -2.0f * tz;
        r0.st = fmaf(tx, tx, fmaf(ty, ty, tz * tz));
        r0.nuc = (is_dna[ig0] != 0 || is_rna[ig0] != 0) ? 1.0f : 0.0f;
    }
    {
        float px = pred[3 * ig1 + 0], py = pred[3 * ig1 + 1], pz = pred[3 * ig1 + 2];
        float tx = truec[3 * ig1 + 0], ty = truec[3 * ig1 + 1], tz = truec[3 * ig1 + 2];
        r1.ax = -2.0f * px; r1.ay = -2.0f * py; r1.az = -2.0f * pz;
        r1.sp = fmaf(px, px, fmaf(py, py, pz * pz));
        r1.bx = -2.0f * tx; r1.by = -2.0f * ty; r1.bz = -2.0f * tz;
        r1.st = fmaf(tx, tx, fmaf(ty, ty, tz * tz));
        r1.nuc = (is_dna[ig1] != 0 || is_rna[ig1] != 0) ? 1.0f : 0.0f;
    }
    const float cm0 = (cmask[ig0] != 0) ? 1.0f : 0.0f;
    const float cm1 = (cmask[ig1] != 0) ? 1.0f : 0.0f;

    __syncthreads();

    float n0 = 0.0f, d0 = 0.0f, n1 = 0.0f, d1 = 0.0f;

    if (hot) {
        #pragma unroll 2
        for (int j = 0; j < TJ; ++j) {
            float4 A = sA[j];
            float4 B = sB[j];
            float cj = sC[j];
            pair_dot(r0, A, B, cj, tbl, n0, d0, true);
            pair_dot(r1, A, B, cj, tbl, n1, d1, true);
        }
    } else {
        const int i0 = I * TI + tid;
        const int i1 = i0 + BLK;
        const int jbase = Jh * TJ;
        #pragma unroll 2
        for (int j = 0; j < TJ; ++j) {
            float4 A = sA[j];
            float4 B = sB[j];
            float cj = sC[j];
            const int jcol = jbase + j;
            pair_dot(r0, A, B, cj, tbl, n0, d0, jcol > i0);
            pair_dot(r1, A, B, cj, tbl, n1, d1, jcol > i1);
        }
    }

    float acc_num = fmaf(n0, cm0, n1 * cm1);
    float acc_den = fmaf(d0, cm0, d1 * cm1);

    #pragma unroll
    for (int o = 16; o > 0; o >>= 1) {
        acc_num += __shfl_xor_sync(0xFFFFFFFFu, acc_num, o);
        acc_den += __shfl_xor_sync(0xFFFFFFFFu, acc_den, o);
    }
    __shared__ float rn[BLK / 32], rd[BLK / 32];
    const int wid = tid >> 5;
    if ((tid & 31) == 0) { rn[wid] = acc_num; rd[wid] = acc_den; }
    __syncthreads();

    if (tid == 0) {
        float tn = rn[0] + rn[1] + rn[2] + rn[3];
        float td = rd[0] + rd[1] + rd[2] + rd[3];
        atomicAdd(&g_acc[2 * b + 0], (double)tn);
        atomicAdd(&g_acc[2 * b + 1], (double)td);
        __threadfence();
        int done = atomicAdd(&g_done, 1);
        if (done == TOTAL_CTAS - 1) {
            volatile double* acc = g_acc;
            double num0 = acc[0], den0 = acc[1], num1 = acc[2], den1 = acc[3];
            double e0 = 2.0 * den0; if (e0 < 1.0) e0 = 1.0;
            double e1 = 2.0 * den1; if (e1 < 1.0) e1 = 1.0;
            double l0 = (0.5 * num0) / e0;   // 2 * 0.25 * num / (2*den)
            double l1 = (0.5 * num1) / e1;
            out[0] = (float)(1.0 - 0.5 * (l0 + l1));
            acc[0] = 0.0; acc[1] = 0.0; acc[2] = 0.0; acc[3] = 0.0;
            g_done = 0;
            __threadfence();
        }
    }
}

extern "C" void kernel_launch(void* const* d_in, const int* in_sizes, int n_in,
                              void* d_out, int out_size) {
    const float* pred  = (const float*)d_in[0];
    const float* truec = (const float*)d_in[1];
    const int*   dna   = (const int*)d_in[2];
    const int*   rna   = (const int*)d_in[3];
    const int*   cm    = (const int*)d_in[4];

    lddt_fused<<<TOTAL_CTAS, BLK>>>(pred, truec, dna, rna, cm, (float*)d_out);
}